// round 15
// baseline (speedup 1.0000x reference)
#include <cuda_runtime.h>
#include <cuda_bf16.h>
#include <cstdint>

// ---------------- problem constants ----------------
#define N_TOKENS 16384
#define D_MODEL  4096
#define N_EXP    64
#define N_OUT    128            // gate(64) || noise(64) logits
#define KC       32             // K chunk
#define ASTR     40             // smem row stride in bf16 (conflict-free for frag loads)
#define STG_ELEM (128 * ASTR)   // bf16 elements per stage per array = 5120
#define STG_BYTE (STG_ELEM * 2) // 10240
#define NC       (D_MODEL / KC) // 128 chunks
#define GSMEM    (8 * STG_BYTE) // 81920 B (also holds 128x130 f32 logit tile = 66560 B)
#define LSTR     130            // logit tile row stride (floats)
#define TAU      1.5e-4f        // near-tie refinement threshold (>=10 sigma of GEMM error)

// ---------------- device scratch (no allocs allowed) ----------------
__device__ float          g_logits[(size_t)N_TOKENS * N_OUT];   // exact logits for flagged tokens only
__device__ __nv_bfloat16  g_bhi[(size_t)N_OUT * D_MODEL];       // W^T hi  [n][k]
__device__ __nv_bfloat16  g_blo[(size_t)N_OUT * D_MODEL];       // W^T lo  [n][k]
__device__ float          g_wt [(size_t)N_OUT * D_MODEL];       // W^T fp32 [n][k] (for exact refine)
__device__ float          g_imp[N_EXP];
__device__ float          g_load[N_EXP];
__device__ int            g_nflag;
__device__ int            g_flag[N_TOKENS];

// ---------------- cp.async helpers ----------------
#define CP_ASYNC16(dst, src)                                                        \
    asm volatile("cp.async.cg.shared.global [%0], [%1], 16;\n" ::"r"(dst), "l"(src))
#define CP_COMMIT()  asm volatile("cp.async.commit_group;\n" ::)
#define CP_WAIT1()   asm volatile("cp.async.wait_group 1;\n" ::)

// ---------------- gating helper ----------------
__device__ __forceinline__ void warp_argmax(float& v, int& i) {
#pragma unroll
    for (int o = 16; o; o >>= 1) {
        float ov = __shfl_xor_sync(0xffffffffu, v, o);
        int   oi = __shfl_xor_sync(0xffffffffu, i, o);
        if (ov > v || (ov == v && oi < i)) { v = ov; i = oi; }
    }
}

// ---------------- prep: smem-tiled transpose + bf16 split + fp32 copy ----------------
__global__ void __launch_bounds__(256) prep_kernel(const float* __restrict__ wg,
                                                   const float* __restrict__ wn) {
    __shared__ float sT[64][65];
    const int tid  = threadIdx.x;
    const int half = blockIdx.x & 1;           // 0: gate, 1: noise
    const int k0   = (blockIdx.x >> 1) * 64;
    const float* src = half ? wn : wg;

    if (blockIdx.x == 0) {
        if (tid < N_EXP) { g_imp[tid] = 0.f; g_load[tid] = 0.f; }
        if (tid == N_EXP) g_nflag = 0;
    }

    for (int i = tid; i < 64 * 64; i += 256) {
        int r = i >> 6, c = i & 63;
        sT[c][r] = src[(size_t)(k0 + r) * N_EXP + c];
    }
    __syncthreads();

    const int n  = tid >> 2;
    const int kq = (tid & 3) * 16;
    __nv_bfloat16 hb[16], lb[16];
    float wb[16];
#pragma unroll
    for (int j = 0; j < 16; j++) {
        float w = sT[n][kq + j];
        __nv_bfloat16 h = __float2bfloat16(w);
        hb[j] = h;
        lb[j] = __float2bfloat16(w - __bfloat162float(h));
        wb[j] = w;
    }
    const size_t ob = (size_t)(half * 64 + n) * D_MODEL + k0 + kq;
    uint4* dh = reinterpret_cast<uint4*>(g_bhi + ob);
    uint4* dl = reinterpret_cast<uint4*>(g_blo + ob);
    uint4* dw = reinterpret_cast<uint4*>(g_wt  + ob);
    dh[0] = reinterpret_cast<const uint4*>(hb)[0];
    dh[1] = reinterpret_cast<const uint4*>(hb)[1];
    dl[0] = reinterpret_cast<const uint4*>(lb)[0];
    dl[1] = reinterpret_cast<const uint4*>(lb)[1];
#pragma unroll
    for (int j = 0; j < 4; j++) dw[j] = reinterpret_cast<const uint4*>(wb)[j];
}

// ---------------- GEMM + fused gate ----------------
#define MMA_BF16(d, a, b0v, b1v)                                                    \
    asm volatile("mma.sync.aligned.m16n8k16.row.col.f32.bf16.bf16.f32 "             \
                 "{%0,%1,%2,%3}, {%4,%5,%6,%7}, {%8,%9}, {%0,%1,%2,%3};"            \
                 : "+f"(d[0]), "+f"(d[1]), "+f"(d[2]), "+f"(d[3])                   \
                 : "r"(a[0]), "r"(a[1]), "r"(a[2]), "r"(a[3]), "r"(b0v), "r"(b1v))

__global__ void __launch_bounds__(256) gemm_kernel(const float* __restrict__ inp,
                                                   const float* __restrict__ noise,
                                                   float* __restrict__ out) {
    extern __shared__ __nv_bfloat16 sm[];
    __nv_bfloat16* sAhi = sm;                    // [2][STG_ELEM]
    __nv_bfloat16* sAlo = sm + 2 * STG_ELEM;
    __nv_bfloat16* sBhi = sm + 4 * STG_ELEM;
    __nv_bfloat16* sBlo = sm + 6 * STG_ELEM;

    __shared__ float s_imp[N_EXP];
    __shared__ float s_load[N_EXP];

    const int tid  = threadIdx.x;
    const int wid  = tid >> 5, lane = tid & 31;
    const int wm   = wid & 3;          // warp row tile (32 rows)
    const int wn   = wid >> 2;         // warp col tile (64 cols)
    const int g    = lane >> 2, tg = lane & 3;
    const int row0 = blockIdx.x * 128;

    if (tid < N_EXP) { s_imp[tid] = 0.f; s_load[tid] = 0.f; }

    float acc[2][8][4];
#pragma unroll
    for (int a = 0; a < 2; a++)
#pragma unroll
        for (int b = 0; b < 8; b++)
#pragma unroll
            for (int c = 0; c < 4; c++) acc[a][b][c] = 0.f;

    const int lr = tid >> 1;           // load row (A) / n (B)
    const int lc = (tid & 1) * 16;     // col base within chunk

    const float* aSrc = inp + (size_t)(row0 + lr) * D_MODEL + lc;
    const __nv_bfloat16* bhSrc = g_bhi + (size_t)lr * D_MODEL + lc;
    const __nv_bfloat16* blSrc = g_blo + (size_t)lr * D_MODEL + lc;
    const uint32_t sBhiAddr = (uint32_t)__cvta_generic_to_shared(sBhi) + (lr * ASTR + lc) * 2;
    const uint32_t sBloAddr = (uint32_t)__cvta_generic_to_shared(sBlo) + (lr * ASTR + lc) * 2;

    float4 aR[4];

#define CPB(c, s)                                                          \
    do {                                                                   \
        CP_ASYNC16(sBhiAddr + (s)*STG_BYTE,      bhSrc + (c)*KC);          \
        CP_ASYNC16(sBhiAddr + (s)*STG_BYTE + 16, bhSrc + (c)*KC + 8);      \
        CP_ASYNC16(sBloAddr + (s)*STG_BYTE,      blSrc + (c)*KC);          \
        CP_ASYNC16(sBloAddr + (s)*STG_BYTE + 16, blSrc + (c)*KC + 8);      \
    } while (0)

#define LDA(c)                                                             \
    do {                                                                   \
        _Pragma("unroll")                                                  \
        for (int u = 0; u < 4; u++)                                        \
            aR[u] = *reinterpret_cast<const float4*>(aSrc + (c)*KC + u*4); \
    } while (0)

#define CONVSTORE(s)                                                                   \
    do {                                                                               \
        int off0 = (s)*STG_ELEM + lr * ASTR + lc;                                      \
        _Pragma("unroll")                                                              \
        for (int u = 0; u < 4; u++) {                                                  \
            float4 v = aR[u];                                                          \
            __nv_bfloat16 h0 = __float2bfloat16(v.x);                                  \
            __nv_bfloat16 h1 = __float2bfloat16(v.y);                                  \
            __nv_bfloat16 h2 = __float2bfloat16(v.z);                                  \
            __nv_bfloat16 h3 = __float2bfloat16(v.w);                                  \
            __nv_bfloat16 l0 = __float2bfloat16(v.x - __bfloat162float(h0));           \
            __nv_bfloat16 l1 = __float2bfloat16(v.y - __bfloat162float(h1));           \
            __nv_bfloat16 l2 = __float2bfloat16(v.z - __bfloat162float(h2));           \
            __nv_bfloat16 l3 = __float2bfloat16(v.w - __bfloat162float(h3));           \
            int off = off0 + u * 4;                                                    \
            *reinterpret_cast<__nv_bfloat162*>(&sAhi[off])     = __halves2bfloat162(h0, h1); \
            *reinterpret_cast<__nv_bfloat162*>(&sAhi[off + 2]) = __halves2bfloat162(h2, h3); \
            *reinterpret_cast<__nv_bfloat162*>(&sAlo[off])     = __halves2bfloat162(l0, l1); \
            *reinterpret_cast<__nv_bfloat162*>(&sAlo[off + 2]) = __halves2bfloat162(l2, l3); \
        }                                                                              \
    } while (0)

    // ---- prologue ----
    LDA(0);
    CPB(0, 0); CP_COMMIT();        // group for chunk 0
    CONVSTORE(0);
    CPB(1, 1); CP_COMMIT();        // group for chunk 1
    LDA(1);
    CP_WAIT1();                    // chunk 0 B landed
    __syncthreads();

    for (int i = 0; i < NC; i++) {
        const int p = i & 1;
        const int ab = p * STG_ELEM;

#pragma unroll
        for (int ks = 0; ks < KC; ks += 16) {
            uint32_t ah[2][4], al[2][4];
#pragma unroll
            for (int mi = 0; mi < 2; mi++) {
                int r = wm * 32 + mi * 16 + g;
                int c = ks + tg * 2;
                ah[mi][0] = *reinterpret_cast<const uint32_t*>(&sAhi[ab + r * ASTR + c]);
                ah[mi][1] = *reinterpret_cast<const uint32_t*>(&sAhi[ab + (r + 8) * ASTR + c]);
                ah[mi][2] = *reinterpret_cast<const uint32_t*>(&sAhi[ab + r * ASTR + c + 8]);
                ah[mi][3] = *reinterpret_cast<const uint32_t*>(&sAhi[ab + (r + 8) * ASTR + c + 8]);
                al[mi][0] = *reinterpret_cast<const uint32_t*>(&sAlo[ab + r * ASTR + c]);
                al[mi][1] = *reinterpret_cast<const uint32_t*>(&sAlo[ab + (r + 8) * ASTR + c]);
                al[mi][2] = *reinterpret_cast<const uint32_t*>(&sAlo[ab + r * ASTR + c + 8]);
                al[mi][3] = *reinterpret_cast<const uint32_t*>(&sAlo[ab + (r + 8) * ASTR + c + 8]);
            }
            // hoist all B fragments for this ks (8 ni x {hi0,hi1,lo0,lo1})
            uint32_t bhf[8][2], blf[8][2];
#pragma unroll
            for (int ni = 0; ni < 8; ni++) {
                int nn = wn * 64 + ni * 8 + g;
                bhf[ni][0] = *reinterpret_cast<const uint32_t*>(&sBhi[ab + nn * ASTR + ks + tg * 2]);
                bhf[ni][1] = *reinterpret_cast<const uint32_t*>(&sBhi[ab + nn * ASTR + ks + tg * 2 + 8]);
                blf[ni][0] = *reinterpret_cast<const uint32_t*>(&sBlo[ab + nn * ASTR + ks + tg * 2]);
                blf[ni][1] = *reinterpret_cast<const uint32_t*>(&sBlo[ab + nn * ASTR + ks + tg * 2 + 8]);
            }
            // pass 1: hi*hi over all 16 accs
#pragma unroll
            for (int ni = 0; ni < 8; ni++)
#pragma unroll
                for (int mi = 0; mi < 2; mi++)
                    MMA_BF16(acc[mi][ni], ah[mi], bhf[ni][0], bhf[ni][1]);
            // pass 2: lo*hi
#pragma unroll
            for (int ni = 0; ni < 8; ni++)
#pragma unroll
                for (int mi = 0; mi < 2; mi++)
                    MMA_BF16(acc[mi][ni], al[mi], bhf[ni][0], bhf[ni][1]);
            // pass 3: hi*lo
#pragma unroll
            for (int ni = 0; ni < 8; ni++)
#pragma unroll
                for (int mi = 0; mi < 2; mi++)
                    MMA_BF16(acc[mi][ni], ah[mi], blf[ni][0], blf[ni][1]);
        }
        __syncthreads();                         // all warps done reading stage p

        if (i + 1 < NC) {
            CONVSTORE(p ^ 1);                    // A for chunk i+1 (held in aR)
            if (i + 2 < NC) { CPB(i + 2, p); }   // B for chunk i+2 into freed stage p
            CP_COMMIT();                         // always commit (empty group ok)
            if (i + 2 < NC) { LDA(i + 2); }
            CP_WAIT1();                          // chunk i+1's B group complete
            __syncthreads();
        }
    }

    // ---- epilogue phase 1: stage logits into smem tile [128][LSTR] ----
    __syncthreads();                             // last MMA reads done; smem reusable
    float* sL = reinterpret_cast<float*>(sm);    // 128*130*4 = 66560 B <= 81920 B
#pragma unroll
    for (int mi = 0; mi < 2; mi++)
#pragma unroll
        for (int ni = 0; ni < 8; ni++) {
            int r = wm * 32 + mi * 16 + g;
            int c = wn * 64 + ni * 8 + tg * 2;
            sL[r * LSTR + c]           = acc[mi][ni][0];
            sL[r * LSTR + c + 1]       = acc[mi][ni][1];
            sL[(r + 8) * LSTR + c]     = acc[mi][ni][2];
            sL[(r + 8) * LSTR + c + 1] = acc[mi][ni][3];
        }
    __syncthreads();

    // ---- epilogue phase 2: fused gate (identical math to the old gate_kernel) ----
    {
        const int e0 = 2 * lane, e1 = 2 * lane + 1;
        float li0 = 0.f, li1 = 0.f, ll0 = 0.f, ll1 = 0.f;

        for (int it = 0; it < 16; it++) {
            const int lrow = wid * 16 + it;
            const int t    = row0 + lrow;
            const float* rowp = sL + lrow * LSTR;
            float cl0 = rowp[e0],      cl1 = rowp[e1];
            float rn0 = rowp[64 + e0], rn1 = rowp[64 + e1];
            float2 nz = *reinterpret_cast<const float2*>(noise + (size_t)t * N_EXP + e0);

            float sp0 = fmaxf(rn0, 0.f) + log1pf(expf(-fabsf(rn0))) + 0.01f;
            float sp1 = fmaxf(rn1, 0.f) + log1pf(expf(-fabsf(rn1))) + 0.01f;
            float ny0 = cl0 + nz.x * sp0;
            float ny1 = cl1 + nz.y * sp1;

            // top-3 with stable (lower index) tie-break
            float bv; int bi;
            if (ny0 >= ny1) { bv = ny0; bi = e0; } else { bv = ny1; bi = e1; }
            warp_argmax(bv, bi);
            float m1 = bv; int j1 = bi;

            float w0 = (e0 == j1) ? -3.4e38f : ny0;
            float w1 = (e1 == j1) ? -3.4e38f : ny1;
            if (w0 >= w1) { bv = w0; bi = e0; } else { bv = w1; bi = e1; }
            warp_argmax(bv, bi);
            float m2 = bv; int j2 = bi;

            w0 = (e0 == j2) ? -3.4e38f : w0;
            w1 = (e1 == j2) ? -3.4e38f : w1;
            if (w0 >= w1) { bv = w0; bi = e0; } else { bv = w1; bi = e1; }
            warp_argmax(bv, bi);
            float m3 = bv;

            // near-tie? defer the whole token to the exact refine pass
            bool flagged = (m1 - m2 < TAU) || (m2 - m3 < TAU);
            if (flagged) {
                if (lane == 0) {
                    int s = atomicAdd(&g_nflag, 1);
                    g_flag[s] = t;
                }
                continue;
            }

            float ee  = expf(m2 - m1);
            float inv = 1.f / (1.f + ee);
            float gg0 = inv, gg1 = ee * inv;

            if (lane == 0) {
                out[2 * t]                    = (float)j1;
                out[2 * t + 1]                = (float)j2;
                out[2 * N_TOKENS + 2 * t]     = gg0;
                out[2 * N_TOKENS + 2 * t + 1] = gg1;
            }

            if (e0 == j1) li0 += gg0; else if (e0 == j2) li0 += gg1;
            if (e1 == j1) li1 += gg0; else if (e1 == j2) li1 += gg1;

            float thr0 = (ny0 > m3) ? m3 : m2;
            float thr1 = (ny1 > m3) ? m3 : m2;
            ll0 += normcdff((cl0 - thr0) / sp0);
            ll1 += normcdff((cl1 - thr1) / sp1);
        }

        atomicAdd(&s_imp[e0], li0);  atomicAdd(&s_imp[e1], li1);
        atomicAdd(&s_load[e0], ll0); atomicAdd(&s_load[e1], ll1);
        __syncthreads();
        if (tid < N_EXP) {
            atomicAdd(&g_imp[tid],  s_imp[tid]);
            atomicAdd(&g_load[tid], s_load[tid]);
        }
    }
#undef CPB
#undef LDA
#undef CONVSTORE
}

// ---------------- refine: fp64-exact logits, 128 token-slots x 128 cols ----------------
__global__ void __launch_bounds__(256) refine_kernel(const float* __restrict__ inp) {
    const int tid  = threadIdx.x;
    const int lane = tid & 31;
    const int W    = blockIdx.x * 8 + (tid >> 5);   // 0..16383
    const int slot = W >> 7;                        // 128 token slots
    const int n    = W & 127;                       // output column
    const int nf   = g_nflag;

    for (int ii = slot; ii < nf; ii += 128) {
        const int t = g_flag[ii];
        const float4* ap = reinterpret_cast<const float4*>(inp + (size_t)t * D_MODEL);
        const float4* wp = reinterpret_cast<const float4*>(g_wt + (size_t)n * D_MODEL);
        double c0 = 0, c1 = 0, c2 = 0, c3 = 0;
#pragma unroll 8
        for (int j = 0; j < D_MODEL / 128; j++) {   // 32 iters, lane-strided float4
            float4 a = ap[j * 32 + lane];
            float4 b = wp[j * 32 + lane];
            c0 = fma((double)a.x, (double)b.x, c0);
            c1 = fma((double)a.y, (double)b.y, c1);
            c2 = fma((double)a.z, (double)b.z, c2);
            c3 = fma((double)a.w, (double)b.w, c3);
        }
        double s = (c0 + c1) + (c2 + c3);
#pragma unroll
        for (int o = 16; o; o >>= 1) s += __shfl_down_sync(0xffffffffu, s, o);
        if (lane == 0) g_logits[(size_t)t * N_OUT + n] = (float)s;
    }
}

// ---------------- refine2: gate math on exact logits (warp per flagged token) ----------------
__global__ void __launch_bounds__(256) refine2_kernel(const float* __restrict__ noise,
                                                      float* __restrict__ out) {
    const int tid  = threadIdx.x;
    const int lane = tid & 31;
    const int W    = blockIdx.x * 8 + (tid >> 5);
    const int nW   = gridDim.x * 8;
    const int nf   = g_nflag;
    const int e0 = 2 * lane, e1 = 2 * lane + 1;

    for (int ii = W; ii < nf; ii += nW) {
        const int t = g_flag[ii];
        const float* rowp = g_logits + (size_t)t * N_OUT;
        float cl0 = rowp[e0], cl1 = rowp[e1];
        float rn0 = rowp[64 + e0], rn1 = rowp[64 + e1];
        float nz0 = noise[(size_t)t * N_EXP + e0];
        float nz1 = noise[(size_t)t * N_EXP + e1];

        float sp0 = fmaxf(rn0, 0.f) + log1pf(expf(-fabsf(rn0))) + 0.01f;
        float sp1 = fmaxf(rn1, 0.f) + log1pf(expf(-fabsf(rn1))) + 0.01f;
        float ny0 = cl0 + nz0 * sp0;
        float ny1 = cl1 + nz1 * sp1;

        float bv; int bi;
        if (ny0 >= ny1) { bv = ny0; bi = e0; } else { bv = ny1; bi = e1; }
        warp_argmax(bv, bi);
        float m1 = bv; int j1 = bi;

        float w0 = (e0 == j1) ? -3.4e38f : ny0;
        float w1 = (e1 == j1) ? -3.4e38f : ny1;
        if (w0 >= w1) { bv = w0; bi = e0; } else { bv = w1; bi = e1; }
        warp_argmax(bv, bi);
        float m2 = bv; int j2 = bi;

        w0 = (e0 == j2) ? -3.4e38f : w0;
        w1 = (e1 == j2) ? -3.4e38f : w1;
        if (w0 >= w1) { bv = w0; bi = e0; } else { bv = w1; bi = e1; }
        warp_argmax(bv, bi);
        float m3 = bv;

        float ee  = expf(m2 - m1);
        float inv = 1.f / (1.f + ee);
        float gg0 = inv, gg1 = ee * inv;

        if (lane == 0) {
            out[2 * t]                    = (float)j1;
            out[2 * t + 1]                = (float)j2;
            out[2 * N_TOKENS + 2 * t]     = gg0;
            out[2 * N_TOKENS + 2 * t + 1] = gg1;
        }

        float li0 = 0.f, li1 = 0.f;
        if (e0 == j1) li0 = gg0; else if (e0 == j2) li0 = gg1;
        if (e1 == j1) li1 = gg0; else if (e1 == j2) li1 = gg1;

        float thr0 = (ny0 > m3) ? m3 : m2;
        float thr1 = (ny1 > m3) ? m3 : m2;
        float ll0 = normcdff((cl0 - thr0) / sp0);
        float ll1 = normcdff((cl1 - thr1) / sp1);

        if (li0 != 0.f) atomicAdd(&g_imp[e0], li0);
        if (li1 != 0.f) atomicAdd(&g_imp[e1], li1);
        atomicAdd(&g_load[e0], ll0);
        atomicAdd(&g_load[e1], ll1);
    }
}

// ---------------- loss: cv^2(importance) + cv^2(load), warp-parallel ----------------
__global__ void loss_kernel(float* __restrict__ out) {
    const int lane = threadIdx.x;   // 32 threads
    float loss = 0.f;
#pragma unroll
    for (int pass = 0; pass < 2; pass++) {
        const float* a = pass ? g_load : g_imp;
        float x0 = a[lane], x1 = a[lane + 32];
        float s = x0 + x1;
#pragma unroll
        for (int o = 16; o; o >>= 1) s += __shfl_xor_sync(0xffffffffu, s, o);
        float mean = s * (1.f / 64.f);
        float d0 = x0 - mean, d1 = x1 - mean;
        float v = d0 * d0 + d1 * d1;
#pragma unroll
        for (int o = 16; o; o >>= 1) v += __shfl_xor_sync(0xffffffffu, v, o);
        v *= (1.f / 63.f);
        loss += v / (mean * mean + 1e-10f);
    }
    if (lane == 0) out[2 * N_TOKENS * 2] = loss;   // index 65536
}

// ---------------- launch ----------------
extern "C" void kernel_launch(void* const* d_in, const int* in_sizes, int n_in,
                              void* d_out, int out_size) {
    const float* inp   = (const float*)d_in[0];
    const float* wg    = (const float*)d_in[1];
    const float* wn    = (const float*)d_in[2];
    const float* noise = (const float*)d_in[3];
    float* out = (float*)d_out;

    static bool attr_done = false;
    if (!attr_done) {
        cudaFuncSetAttribute(gemm_kernel, cudaFuncAttributeMaxDynamicSharedMemorySize,
                             GSMEM);
        attr_done = true;
    }

    prep_kernel<<<128, 256>>>(wg, wn);
    gemm_kernel<<<N_TOKENS / 128, 256, GSMEM>>>(inp, noise, out);
    refine_kernel<<<2048, 256>>>(inp);
    refine2_kernel<<<16, 256>>>(noise, out);
    loss_kernel<<<1, 32>>>(out);
}

// round 16
// speedup vs baseline: 1.0318x; 1.0318x over previous
#include <cuda_runtime.h>
#include <cuda_bf16.h>
#include <cstdint>

// ---------------- problem constants ----------------
#define N_TOKENS 16384
#define D_MODEL  4096
#define N_EXP    64
#define N_OUT    128            // gate(64) || noise(64) logits
#define KC       32             // K chunk
#define ASTR     40             // smem row stride in bf16 (conflict-free for frag loads)
#define STG_ELEM (128 * ASTR)   // bf16 elements per stage per array = 5120
#define STG_BYTE (STG_ELEM * 2) // 10240
#define NC       (D_MODEL / KC) // 128 chunks
// layout: sAhi[2] sAlo[2] sBhi[3] sBlo[3] stages
#define GSMEM    (10 * STG_BYTE) // 102400 B (also holds 128x130 f32 logit tile = 66560 B)
#define LSTR     130            // logit tile row stride (floats)
#define TAU      1.5e-4f        // near-tie refinement threshold (>=10 sigma of GEMM error)

// ---------------- device scratch (no allocs allowed) ----------------
__device__ float          g_logits[(size_t)N_TOKENS * N_OUT];   // exact logits for flagged tokens only
__device__ __nv_bfloat16  g_bhi[(size_t)N_OUT * D_MODEL];       // W^T hi  [n][k]
__device__ __nv_bfloat16  g_blo[(size_t)N_OUT * D_MODEL];       // W^T lo  [n][k]
__device__ float          g_wt [(size_t)N_OUT * D_MODEL];       // W^T fp32 [n][k] (for exact refine)
__device__ float          g_imp[N_EXP];
__device__ float          g_load[N_EXP];
__device__ int            g_nflag;
__device__ int            g_flag[N_TOKENS];

// ---------------- cp.async helpers ----------------
#define CP_ASYNC16(dst, src)                                                        \
    asm volatile("cp.async.cg.shared.global [%0], [%1], 16;\n" ::"r"(dst), "l"(src))
#define CP_COMMIT()  asm volatile("cp.async.commit_group;\n" ::)
#define CP_WAIT1()   asm volatile("cp.async.wait_group 1;\n" ::)

// ---------------- gating helper ----------------
__device__ __forceinline__ void warp_argmax(float& v, int& i) {
#pragma unroll
    for (int o = 16; o; o >>= 1) {
        float ov = __shfl_xor_sync(0xffffffffu, v, o);
        int   oi = __shfl_xor_sync(0xffffffffu, i, o);
        if (ov > v || (ov == v && oi < i)) { v = ov; i = oi; }
    }
}

// ---------------- prep: smem-tiled transpose + bf16 split + fp32 copy ----------------
__global__ void __launch_bounds__(256) prep_kernel(const float* __restrict__ wg,
                                                   const float* __restrict__ wn) {
    __shared__ float sT[64][65];
    const int tid  = threadIdx.x;
    const int half = blockIdx.x & 1;           // 0: gate, 1: noise
    const int k0   = (blockIdx.x >> 1) * 64;
    const float* src = half ? wn : wg;

    if (blockIdx.x == 0) {
        if (tid < N_EXP) { g_imp[tid] = 0.f; g_load[tid] = 0.f; }
        if (tid == N_EXP) g_nflag = 0;
    }

    for (int i = tid; i < 64 * 64; i += 256) {
        int r = i >> 6, c = i & 63;
        sT[c][r] = src[(size_t)(k0 + r) * N_EXP + c];
    }
    __syncthreads();

    const int n  = tid >> 2;
    const int kq = (tid & 3) * 16;
    __nv_bfloat16 hb[16], lb[16];
    float wb[16];
#pragma unroll
    for (int j = 0; j < 16; j++) {
        float w = sT[n][kq + j];
        __nv_bfloat16 h = __float2bfloat16(w);
        hb[j] = h;
        lb[j] = __float2bfloat16(w - __bfloat162float(h));
        wb[j] = w;
    }
    const size_t ob = (size_t)(half * 64 + n) * D_MODEL + k0 + kq;
    uint4* dh = reinterpret_cast<uint4*>(g_bhi + ob);
    uint4* dl = reinterpret_cast<uint4*>(g_blo + ob);
    uint4* dw = reinterpret_cast<uint4*>(g_wt  + ob);
    dh[0] = reinterpret_cast<const uint4*>(hb)[0];
    dh[1] = reinterpret_cast<const uint4*>(hb)[1];
    dl[0] = reinterpret_cast<const uint4*>(lb)[0];
    dl[1] = reinterpret_cast<const uint4*>(lb)[1];
#pragma unroll
    for (int j = 0; j < 4; j++) dw[j] = reinterpret_cast<const uint4*>(wb)[j];
}

// ---------------- GEMM + fused gate: single-barrier pipeline (v6) ----------------
#define MMA_BF16(d, a, b0v, b1v)                                                    \
    asm volatile("mma.sync.aligned.m16n8k16.row.col.f32.bf16.bf16.f32 "             \
                 "{%0,%1,%2,%3}, {%4,%5,%6,%7}, {%8,%9}, {%0,%1,%2,%3};"            \
                 : "+f"(d[0]), "+f"(d[1]), "+f"(d[2]), "+f"(d[3])                   \
                 : "r"(a[0]), "r"(a[1]), "r"(a[2]), "r"(a[3]), "r"(b0v), "r"(b1v))

__global__ void __launch_bounds__(256) gemm_kernel(const float* __restrict__ inp,
                                                   const float* __restrict__ noise,
                                                   float* __restrict__ out) {
    extern __shared__ __nv_bfloat16 sm[];
    __nv_bfloat16* sAhi = sm;                    // [2][STG_ELEM]
    __nv_bfloat16* sAlo = sm + 2 * STG_ELEM;     // [2][STG_ELEM]
    __nv_bfloat16* sBhi = sm + 4 * STG_ELEM;     // [3][STG_ELEM]
    __nv_bfloat16* sBlo = sm + 7 * STG_ELEM;     // [3][STG_ELEM]

    __shared__ float s_imp[N_EXP];
    __shared__ float s_load[N_EXP];

    const int tid  = threadIdx.x;
    const int wid  = tid >> 5, lane = tid & 31;
    const int wm   = wid & 3;          // warp row tile (32 rows)
    const int wn   = wid >> 2;         // warp col tile (64 cols)
    const int g    = lane >> 2, tg = lane & 3;
    const int row0 = blockIdx.x * 128;

    if (tid < N_EXP) { s_imp[tid] = 0.f; s_load[tid] = 0.f; }

    float acc[2][8][4];
#pragma unroll
    for (int a = 0; a < 2; a++)
#pragma unroll
        for (int b = 0; b < 8; b++)
#pragma unroll
            for (int c = 0; c < 4; c++) acc[a][b][c] = 0.f;

    const int lr = tid >> 1;           // load row (A) / n (B)
    const int lc = (tid & 1) * 16;     // col base within chunk

    const float* aSrc = inp + (size_t)(row0 + lr) * D_MODEL + lc;
    const __nv_bfloat16* bhSrc = g_bhi + (size_t)lr * D_MODEL + lc;
    const __nv_bfloat16* blSrc = g_blo + (size_t)lr * D_MODEL + lc;
    const uint32_t sBhiAddr = (uint32_t)__cvta_generic_to_shared(sBhi) + (lr * ASTR + lc) * 2;
    const uint32_t sBloAddr = (uint32_t)__cvta_generic_to_shared(sBlo) + (lr * ASTR + lc) * 2;

    float4 aR[4];

#define CPB(c, s)                                                          \
    do {                                                                   \
        CP_ASYNC16(sBhiAddr + (s)*STG_BYTE,      bhSrc + (c)*KC);          \
        CP_ASYNC16(sBhiAddr + (s)*STG_BYTE + 16, bhSrc + (c)*KC + 8);      \
        CP_ASYNC16(sBloAddr + (s)*STG_BYTE,      blSrc + (c)*KC);          \
        CP_ASYNC16(sBloAddr + (s)*STG_BYTE + 16, blSrc + (c)*KC + 8);      \
    } while (0)

#define LDA(c)                                                             \
    do {                                                                   \
        _Pragma("unroll")                                                  \
        for (int u = 0; u < 4; u++)                                        \
            aR[u] = *reinterpret_cast<const float4*>(aSrc + (c)*KC + u*4); \
    } while (0)

#define CONVSTORE(s)                                                                   \
    do {                                                                               \
        int off0 = (s)*STG_ELEM + lr * ASTR + lc;                                      \
        _Pragma("unroll")                                                              \
        for (int u = 0; u < 4; u++) {                                                  \
            float4 v = aR[u];                                                          \
            __nv_bfloat16 h0 = __float2bfloat16(v.x);                                  \
            __nv_bfloat16 h1 = __float2bfloat16(v.y);                                  \
            __nv_bfloat16 h2 = __float2bfloat16(v.z);                                  \
            __nv_bfloat16 h3 = __float2bfloat16(v.w);                                  \
            __nv_bfloat16 l0 = __float2bfloat16(v.x - __bfloat162float(h0));           \
            __nv_bfloat16 l1 = __float2bfloat16(v.y - __bfloat162float(h1));           \
            __nv_bfloat16 l2 = __float2bfloat16(v.z - __bfloat162float(h2));           \
            __nv_bfloat16 l3 = __float2bfloat16(v.w - __bfloat162float(h3));           \
            int off = off0 + u * 4;                                                    \
            *reinterpret_cast<__nv_bfloat162*>(&sAhi[off])     = __halves2bfloat162(h0, h1); \
            *reinterpret_cast<__nv_bfloat162*>(&sAhi[off + 2]) = __halves2bfloat162(h2, h3); \
            *reinterpret_cast<__nv_bfloat162*>(&sAlo[off])     = __halves2bfloat162(l0, l1); \
            *reinterpret_cast<__nv_bfloat162*>(&sAlo[off + 2]) = __halves2bfloat162(l2, l3); \
        }                                                                              \
    } while (0)

    // ---- prologue: A stage 0 (chunk 0), B stages 0,1 (chunks 0,1), aR = chunk 1 ----
    LDA(0);
    CPB(0, 0); CP_COMMIT();        // group: chunk 0
    CONVSTORE(0);
    CPB(1, 1); CP_COMMIT();        // group: chunk 1
    LDA(1);
    CP_WAIT1();                    // chunk 0 B landed (chunk 1 may be in flight)
    __syncthreads();               // visibility of A stage 0 + B stage 0

    int bs = 0;                    // B stage of current chunk (= i % 3)
    for (int i = 0; i < NC; i++) {
        const int pa = i & 1;      // A stage of current chunk
        const int ab = pa * STG_ELEM;
        const int bb = bs * STG_ELEM;

        // ---- producers first (targets last read at iter i-1, protected by its barrier) ----
        if (i + 1 < NC) CONVSTORE(pa ^ 1);           // A chunk i+1 (from aR)
        int bnext = bs + 2; if (bnext >= 3) bnext -= 3;
        if (i + 2 < NC) { CPB(i + 2, bnext); }       // B chunk i+2
        CP_COMMIT();                                 // always commit (empty ok)
        if (i + 2 < NC) { LDA(i + 2); }
        CP_WAIT1();                                  // chunk i+1's B group retired

        // ---- MMA on A stage pa, B stage bs (v2 body, hoisted-B schedule) ----
#pragma unroll
        for (int ks = 0; ks < KC; ks += 16) {
            uint32_t ah[2][4], al[2][4];
#pragma unroll
            for (int mi = 0; mi < 2; mi++) {
                int r = wm * 32 + mi * 16 + g;
                int c = ks + tg * 2;
                ah[mi][0] = *reinterpret_cast<const uint32_t*>(&sAhi[ab + r * ASTR + c]);
                ah[mi][1] = *reinterpret_cast<const uint32_t*>(&sAhi[ab + (r + 8) * ASTR + c]);
                ah[mi][2] = *reinterpret_cast<const uint32_t*>(&sAhi[ab + r * ASTR + c + 8]);
                ah[mi][3] = *reinterpret_cast<const uint32_t*>(&sAhi[ab + (r + 8) * ASTR + c + 8]);
                al[mi][0] = *reinterpret_cast<const uint32_t*>(&sAlo[ab + r * ASTR + c]);
                al[mi][1] = *reinterpret_cast<const uint32_t*>(&sAlo[ab + (r + 8) * ASTR + c]);
                al[mi][2] = *reinterpret_cast<const uint32_t*>(&sAlo[ab + r * ASTR + c + 8]);
                al[mi][3] = *reinterpret_cast<const uint32_t*>(&sAlo[ab + (r + 8) * ASTR + c + 8]);
            }
            uint32_t bhf[8][2], blf[8][2];
#pragma unroll
            for (int ni = 0; ni < 8; ni++) {
                int nn = wn * 64 + ni * 8 + g;
                bhf[ni][0] = *reinterpret_cast<const uint32_t*>(&sBhi[bb + nn * ASTR + ks + tg * 2]);
                bhf[ni][1] = *reinterpret_cast<const uint32_t*>(&sBhi[bb + nn * ASTR + ks + tg * 2 + 8]);
                blf[ni][0] = *reinterpret_cast<const uint32_t*>(&sBlo[bb + nn * ASTR + ks + tg * 2]);
                blf[ni][1] = *reinterpret_cast<const uint32_t*>(&sBlo[bb + nn * ASTR + ks + tg * 2 + 8]);
            }
#pragma unroll
            for (int ni = 0; ni < 8; ni++)
#pragma unroll
                for (int mi = 0; mi < 2; mi++)
                    MMA_BF16(acc[mi][ni], ah[mi], bhf[ni][0], bhf[ni][1]);   // hi*hi
#pragma unroll
            for (int ni = 0; ni < 8; ni++)
#pragma unroll
                for (int mi = 0; mi < 2; mi++)
                    MMA_BF16(acc[mi][ni], al[mi], bhf[ni][0], bhf[ni][1]);   // lo*hi
#pragma unroll
            for (int ni = 0; ni < 8; ni++)
#pragma unroll
                for (int mi = 0; mi < 2; mi++)
                    MMA_BF16(acc[mi][ni], ah[mi], blf[ni][0], blf[ni][1]);   // hi*lo
        }
        __syncthreads();                         // single barrier per chunk
        bs++; if (bs == 3) bs = 0;
    }

    // ---- epilogue phase 1: stage logits into smem tile [128][LSTR] ----
    float* sL = reinterpret_cast<float*>(sm);    // 128*130*4 = 66560 B <= 102400 B
#pragma unroll
    for (int mi = 0; mi < 2; mi++)
#pragma unroll
        for (int ni = 0; ni < 8; ni++) {
            int r = wm * 32 + mi * 16 + g;
            int c = wn * 64 + ni * 8 + tg * 2;
            sL[r * LSTR + c]           = acc[mi][ni][0];
            sL[r * LSTR + c + 1]       = acc[mi][ni][1];
            sL[(r + 8) * LSTR + c]     = acc[mi][ni][2];
            sL[(r + 8) * LSTR + c + 1] = acc[mi][ni][3];
        }
    __syncthreads();

    // ---- epilogue phase 2: fused gate (identical math to the old gate_kernel) ----
    {
        const int e0 = 2 * lane, e1 = 2 * lane + 1;
        float li0 = 0.f, li1 = 0.f, ll0 = 0.f, ll1 = 0.f;

        for (int it = 0; it < 16; it++) {
            const int lrow = wid * 16 + it;
            const int t    = row0 + lrow;
            const float* rowp = sL + lrow * LSTR;
            float cl0 = rowp[e0],      cl1 = rowp[e1];
            float rn0 = rowp[64 + e0], rn1 = rowp[64 + e1];
            float2 nz = *reinterpret_cast<const float2*>(noise + (size_t)t * N_EXP + e0);

            float sp0 = fmaxf(rn0, 0.f) + log1pf(expf(-fabsf(rn0))) + 0.01f;
            float sp1 = fmaxf(rn1, 0.f) + log1pf(expf(-fabsf(rn1))) + 0.01f;
            float ny0 = cl0 + nz.x * sp0;
            float ny1 = cl1 + nz.y * sp1;

            float bv; int bi;
            if (ny0 >= ny1) { bv = ny0; bi = e0; } else { bv = ny1; bi = e1; }
            warp_argmax(bv, bi);
            float m1 = bv; int j1 = bi;

            float w0 = (e0 == j1) ? -3.4e38f : ny0;
            float w1 = (e1 == j1) ? -3.4e38f : ny1;
            if (w0 >= w1) { bv = w0; bi = e0; } else { bv = w1; bi = e1; }
            warp_argmax(bv, bi);
            float m2 = bv; int j2 = bi;

            w0 = (e0 == j2) ? -3.4e38f : w0;
            w1 = (e1 == j2) ? -3.4e38f : w1;
            if (w0 >= w1) { bv = w0; bi = e0; } else { bv = w1; bi = e1; }
            warp_argmax(bv, bi);
            float m3 = bv;

            bool flagged = (m1 - m2 < TAU) || (m2 - m3 < TAU);
            if (flagged) {
                if (lane == 0) {
                    int s = atomicAdd(&g_nflag, 1);
                    g_flag[s] = t;
                }
                continue;
            }

            float ee  = expf(m2 - m1);
            float inv = 1.f / (1.f + ee);
            float gg0 = inv, gg1 = ee * inv;

            if (lane == 0) {
                out[2 * t]                    = (float)j1;
                out[2 * t + 1]                = (float)j2;
                out[2 * N_TOKENS + 2 * t]     = gg0;
                out[2 * N_TOKENS + 2 * t + 1] = gg1;
            }

            if (e0 == j1) li0 += gg0; else if (e0 == j2) li0 += gg1;
            if (e1 == j1) li1 += gg0; else if (e1 == j2) li1 += gg1;

            float thr0 = (ny0 > m3) ? m3 : m2;
            float thr1 = (ny1 > m3) ? m3 : m2;
            ll0 += normcdff((cl0 - thr0) / sp0);
            ll1 += normcdff((cl1 - thr1) / sp1);
        }

        atomicAdd(&s_imp[e0], li0);  atomicAdd(&s_imp[e1], li1);
        atomicAdd(&s_load[e0], ll0); atomicAdd(&s_load[e1], ll1);
        __syncthreads();
        if (tid < N_EXP) {
            atomicAdd(&g_imp[tid],  s_imp[tid]);
            atomicAdd(&g_load[tid], s_load[tid]);
        }
    }
#undef CPB
#undef LDA
#undef CONVSTORE
}

// ---------------- refine: fp64-exact logits, 128 token-slots x 128 cols ----------------
__global__ void __launch_bounds__(256) refine_kernel(const float* __restrict__ inp) {
    const int tid  = threadIdx.x;
    const int lane = tid & 31;
    const int W    = blockIdx.x * 8 + (tid >> 5);   // 0..16383
    const int slot = W >> 7;                        // 128 token slots
    const int n    = W & 127;                       // output column
    const int nf   = g_nflag;

    for (int ii = slot; ii < nf; ii += 128) {
        const int t = g_flag[ii];
        const float4* ap = reinterpret_cast<const float4*>(inp + (size_t)t * D_MODEL);
        const float4* wp = reinterpret_cast<const float4*>(g_wt + (size_t)n * D_MODEL);
        double c0 = 0, c1 = 0, c2 = 0, c3 = 0;
#pragma unroll 8
        for (int j = 0; j < D_MODEL / 128; j++) {   // 32 iters, lane-strided float4
            float4 a = ap[j * 32 + lane];
            float4 b = wp[j * 32 + lane];
            c0 = fma((double)a.x, (double)b.x, c0);
            c1 = fma((double)a.y, (double)b.y, c1);
            c2 = fma((double)a.z, (double)b.z, c2);
            c3 = fma((double)a.w, (double)b.w, c3);
        }
        double s = (c0 + c1) + (c2 + c3);
#pragma unroll
        for (int o = 16; o; o >>= 1) s += __shfl_down_sync(0xffffffffu, s, o);
        if (lane == 0) g_logits[(size_t)t * N_OUT + n] = (float)s;
    }
}

// ---------------- refine2: gate math on exact logits (warp per flagged token) ----------------
__global__ void __launch_bounds__(256) refine2_kernel(const float* __restrict__ noise,
                                                      float* __restrict__ out) {
    const int tid  = threadIdx.x;
    const int lane = tid & 31;
    const int W    = blockIdx.x * 8 + (tid >> 5);
    const int nW   = gridDim.x * 8;
    const int nf   = g_nflag;
    const int e0 = 2 * lane, e1 = 2 * lane + 1;

    for (int ii = W; ii < nf; ii += nW) {
        const int t = g_flag[ii];
        const float* rowp = g_logits + (size_t)t * N_OUT;
        float cl0 = rowp[e0], cl1 = rowp[e1];
        float rn0 = rowp[64 + e0], rn1 = rowp[64 + e1];
        float nz0 = noise[(size_t)t * N_EXP + e0];
        float nz1 = noise[(size_t)t * N_EXP + e1];

        float sp0 = fmaxf(rn0, 0.f) + log1pf(expf(-fabsf(rn0))) + 0.01f;
        float sp1 = fmaxf(rn1, 0.f) + log1pf(expf(-fabsf(rn1))) + 0.01f;
        float ny0 = cl0 + nz0 * sp0;
        float ny1 = cl1 + nz1 * sp1;

        float bv; int bi;
        if (ny0 >= ny1) { bv = ny0; bi = e0; } else { bv = ny1; bi = e1; }
        warp_argmax(bv, bi);
        float m1 = bv; int j1 = bi;

        float w0 = (e0 == j1) ? -3.4e38f : ny0;
        float w1 = (e1 == j1) ? -3.4e38f : ny1;
        if (w0 >= w1) { bv = w0; bi = e0; } else { bv = w1; bi = e1; }
        warp_argmax(bv, bi);
        float m2 = bv; int j2 = bi;

        w0 = (e0 == j2) ? -3.4e38f : w0;
        w1 = (e1 == j2) ? -3.4e38f : w1;
        if (w0 >= w1) { bv = w0; bi = e0; } else { bv = w1; bi = e1; }
        warp_argmax(bv, bi);
        float m3 = bv;

        float ee  = expf(m2 - m1);
        float inv = 1.f / (1.f + ee);
        float gg0 = inv, gg1 = ee * inv;

        if (lane == 0) {
            out[2 * t]                    = (float)j1;
            out[2 * t + 1]                = (float)j2;
            out[2 * N_TOKENS + 2 * t]     = gg0;
            out[2 * N_TOKENS + 2 * t + 1] = gg1;
        }

        float li0 = 0.f, li1 = 0.f;
        if (e0 == j1) li0 = gg0; else if (e0 == j2) li0 = gg1;
        if (e1 == j1) li1 = gg0; else if (e1 == j2) li1 = gg1;

        float thr0 = (ny0 > m3) ? m3 : m2;
        float thr1 = (ny1 > m3) ? m3 : m2;
        float ll0 = normcdff((cl0 - thr0) / sp0);
        float ll1 = normcdff((cl1 - thr1) / sp1);

        if (li0 != 0.f) atomicAdd(&g_imp[e0], li0);
        if (li1 != 0.f) atomicAdd(&g_imp[e1], li1);
        atomicAdd(&g_load[e0], ll0);
        atomicAdd(&g_load[e1], ll1);
    }
}

// ---------------- loss: cv^2(importance) + cv^2(load), warp-parallel ----------------
__global__ void loss_kernel(float* __restrict__ out) {
    const int lane = threadIdx.x;   // 32 threads
    float loss = 0.f;
#pragma unroll
    for (int pass = 0; pass < 2; pass++) {
        const float* a = pass ? g_load : g_imp;
        float x0 = a[lane], x1 = a[lane + 32];
        float s = x0 + x1;
#pragma unroll
        for (int o = 16; o; o >>= 1) s += __shfl_xor_sync(0xffffffffu, s, o);
        float mean = s * (1.f / 64.f);
        float d0 = x0 - mean, d1 = x1 - mean;
        float v = d0 * d0 + d1 * d1;
#pragma unroll
        for (int o = 16; o; o >>= 1) v += __shfl_xor_sync(0xffffffffu, v, o);
        v *= (1.f / 63.f);
        loss += v / (mean * mean + 1e-10f);
    }
    if (lane == 0) out[2 * N_TOKENS * 2] = loss;   // index 65536
}

// ---------------- launch ----------------
extern "C" void kernel_launch(void* const* d_in, const int* in_sizes, int n_in,
                              void* d_out, int out_size) {
    const float* inp   = (const float*)d_in[0];
    const float* wg    = (const float*)d_in[1];
    const float* wn    = (const float*)d_in[2];
    const float* noise = (const float*)d_in[3];
    float* out = (float*)d_out;

    static bool attr_done = false;
    if (!attr_done) {
        cudaFuncSetAttribute(gemm_kernel, cudaFuncAttributeMaxDynamicSharedMemorySize,
                             GSMEM);
        attr_done = true;
    }

    prep_kernel<<<128, 256>>>(wg, wn);
    gemm_kernel<<<N_TOKENS / 128, 256, GSMEM>>>(inp, noise, out);
    refine_kernel<<<2048, 256>>>(inp);
    refine2_kernel<<<64, 256>>>(noise, out);
    loss_kernel<<<1, 32>>>(out);
}

// round 17
// speedup vs baseline: 1.0942x; 1.0604x over previous
#include <cuda_runtime.h>
#include <cuda_bf16.h>
#include <cstdint>

// ---------------- problem constants ----------------
#define N_TOKENS 16384
#define D_MODEL  4096
#define N_EXP    64
#define N_OUT    128            // gate(64) || noise(64) logits
#define KC       32             // K chunk
#define ASTR     40             // smem row stride in bf16 (conflict-free for frag loads)
#define STG_ELEM (128 * ASTR)   // bf16 elements per stage per array = 5120
#define STG_BYTE (STG_ELEM * 2) // 10240
#define NC       (D_MODEL / KC) // 128 chunks
// layout: sAhi[2] sAlo[2] sBhi[3] sBlo[3] stages
#define GSMEM    (10 * STG_BYTE) // 102400 B (also holds 128x130 f32 logit tile = 66560 B)
#define LSTR     130            // logit tile row stride (floats)
#define TAU      1.5e-4f        // near-tie refinement threshold (>=10 sigma of GEMM error)

// ---------------- device scratch (no allocs allowed) ----------------
__device__ float          g_logits[(size_t)N_TOKENS * N_OUT];   // exact logits for flagged tokens only
__device__ __nv_bfloat16  g_bhi[(size_t)N_OUT * D_MODEL];       // W^T hi  [n][k]
__device__ __nv_bfloat16  g_blo[(size_t)N_OUT * D_MODEL];       // W^T lo  [n][k]
__device__ float          g_wt [(size_t)N_OUT * D_MODEL];       // W^T fp32 [n][k] (for exact refine)
__device__ float          g_imp[N_EXP];
__device__ float          g_load[N_EXP];
__device__ int            g_nflag;
__device__ int            g_flag[N_TOKENS];

// ---------------- cp.async helpers ----------------
#define CP_ASYNC16(dst, src)                                                        \
    asm volatile("cp.async.cg.shared.global [%0], [%1], 16;\n" ::"r"(dst), "l"(src))
#define CP_COMMIT()  asm volatile("cp.async.commit_group;\n" ::)
#define CP_WAIT1()   asm volatile("cp.async.wait_group 1;\n" ::)

// ---------------- gating helper ----------------
__device__ __forceinline__ void warp_argmax(float& v, int& i) {
#pragma unroll
    for (int o = 16; o; o >>= 1) {
        float ov = __shfl_xor_sync(0xffffffffu, v, o);
        int   oi = __shfl_xor_sync(0xffffffffu, i, o);
        if (ov > v || (ov == v && oi < i)) { v = ov; i = oi; }
    }
}

// ---------------- prep: smem-tiled transpose + bf16 split + fp32 copy ----------------
__global__ void __launch_bounds__(256) prep_kernel(const float* __restrict__ wg,
                                                   const float* __restrict__ wn) {
    __shared__ float sT[64][65];
    const int tid  = threadIdx.x;
    const int half = blockIdx.x & 1;           // 0: gate, 1: noise
    const int k0   = (blockIdx.x >> 1) * 64;
    const float* src = half ? wn : wg;

    if (blockIdx.x == 0) {
        if (tid < N_EXP) { g_imp[tid] = 0.f; g_load[tid] = 0.f; }
        if (tid == N_EXP) g_nflag = 0;
    }

    for (int i = tid; i < 64 * 64; i += 256) {
        int r = i >> 6, c = i & 63;
        sT[c][r] = src[(size_t)(k0 + r) * N_EXP + c];
    }
    __syncthreads();

    const int n  = tid >> 2;
    const int kq = (tid & 3) * 16;
    __nv_bfloat16 hb[16], lb[16];
    float wb[16];
#pragma unroll
    for (int j = 0; j < 16; j++) {
        float w = sT[n][kq + j];
        __nv_bfloat16 h = __float2bfloat16(w);
        hb[j] = h;
        lb[j] = __float2bfloat16(w - __bfloat162float(h));
        wb[j] = w;
    }
    const size_t ob = (size_t)(half * 64 + n) * D_MODEL + k0 + kq;
    uint4* dh = reinterpret_cast<uint4*>(g_bhi + ob);
    uint4* dl = reinterpret_cast<uint4*>(g_blo + ob);
    uint4* dw = reinterpret_cast<uint4*>(g_wt  + ob);
    dh[0] = reinterpret_cast<const uint4*>(hb)[0];
    dh[1] = reinterpret_cast<const uint4*>(hb)[1];
    dl[0] = reinterpret_cast<const uint4*>(lb)[0];
    dl[1] = reinterpret_cast<const uint4*>(lb)[1];
#pragma unroll
    for (int j = 0; j < 4; j++) dw[j] = reinterpret_cast<const uint4*>(wb)[j];
}

// ---------------- GEMM + fused gate: single-barrier pipeline, late wait (v7) ----------------
#define MMA_BF16(d, a, b0v, b1v)                                                    \
    asm volatile("mma.sync.aligned.m16n8k16.row.col.f32.bf16.bf16.f32 "             \
                 "{%0,%1,%2,%3}, {%4,%5,%6,%7}, {%8,%9}, {%0,%1,%2,%3};"            \
                 : "+f"(d[0]), "+f"(d[1]), "+f"(d[2]), "+f"(d[3])                   \
                 : "r"(a[0]), "r"(a[1]), "r"(a[2]), "r"(a[3]), "r"(b0v), "r"(b1v))

__global__ void __launch_bounds__(256) gemm_kernel(const float* __restrict__ inp,
                                                   const float* __restrict__ noise,
                                                   float* __restrict__ out) {
    extern __shared__ __nv_bfloat16 sm[];
    __nv_bfloat16* sAhi = sm;                    // [2][STG_ELEM]
    __nv_bfloat16* sAlo = sm + 2 * STG_ELEM;     // [2][STG_ELEM]
    __nv_bfloat16* sBhi = sm + 4 * STG_ELEM;     // [3][STG_ELEM]
    __nv_bfloat16* sBlo = sm + 7 * STG_ELEM;     // [3][STG_ELEM]

    __shared__ float s_imp[N_EXP];
    __shared__ float s_load[N_EXP];

    const int tid  = threadIdx.x;
    const int wid  = tid >> 5, lane = tid & 31;
    const int wm   = wid & 3;          // warp row tile (32 rows)
    const int wn   = wid >> 2;         // warp col tile (64 cols)
    const int g    = lane >> 2, tg = lane & 3;
    const int row0 = blockIdx.x * 128;

    if (tid < N_EXP) { s_imp[tid] = 0.f; s_load[tid] = 0.f; }

    float acc[2][8][4];
#pragma unroll
    for (int a = 0; a < 2; a++)
#pragma unroll
        for (int b = 0; b < 8; b++)
#pragma unroll
            for (int c = 0; c < 4; c++) acc[a][b][c] = 0.f;

    const int lr = tid >> 1;           // load row (A) / n (B)
    const int lc = (tid & 1) * 16;     // col base within chunk

    const float* aSrc = inp + (size_t)(row0 + lr) * D_MODEL + lc;
    const __nv_bfloat16* bhSrc = g_bhi + (size_t)lr * D_MODEL + lc;
    const __nv_bfloat16* blSrc = g_blo + (size_t)lr * D_MODEL + lc;
    const uint32_t sBhiAddr = (uint32_t)__cvta_generic_to_shared(sBhi) + (lr * ASTR + lc) * 2;
    const uint32_t sBloAddr = (uint32_t)__cvta_generic_to_shared(sBlo) + (lr * ASTR + lc) * 2;

    float4 aR[4];

#define CPB(c, s)                                                          \
    do {                                                                   \
        CP_ASYNC16(sBhiAddr + (s)*STG_BYTE,      bhSrc + (c)*KC);          \
        CP_ASYNC16(sBhiAddr + (s)*STG_BYTE + 16, bhSrc + (c)*KC + 8);      \
        CP_ASYNC16(sBloAddr + (s)*STG_BYTE,      blSrc + (c)*KC);          \
        CP_ASYNC16(sBloAddr + (s)*STG_BYTE + 16, blSrc + (c)*KC + 8);      \
    } while (0)

#define LDA(c)                                                             \
    do {                                                                   \
        _Pragma("unroll")                                                  \
        for (int u = 0; u < 4; u++)                                        \
            aR[u] = *reinterpret_cast<const float4*>(aSrc + (c)*KC + u*4); \
    } while (0)

#define CONVSTORE(s)                                                                   \
    do {                                                                               \
        int off0 = (s)*STG_ELEM + lr * ASTR + lc;                                      \
        _Pragma("unroll")                                                              \
        for (int u = 0; u < 4; u++) {                                                  \
            float4 v = aR[u];                                                          \
            __nv_bfloat16 h0 = __float2bfloat16(v.x);                                  \
            __nv_bfloat16 h1 = __float2bfloat16(v.y);                                  \
            __nv_bfloat16 h2 = __float2bfloat16(v.z);                                  \
            __nv_bfloat16 h3 = __float2bfloat16(v.w);                                  \
            __nv_bfloat16 l0 = __float2bfloat16(v.x - __bfloat162float(h0));           \
            __nv_bfloat16 l1 = __float2bfloat16(v.y - __bfloat162float(h1));           \
            __nv_bfloat16 l2 = __float2bfloat16(v.z - __bfloat162float(h2));           \
            __nv_bfloat16 l3 = __float2bfloat16(v.w - __bfloat162float(h3));           \
            int off = off0 + u * 4;                                                    \
            *reinterpret_cast<__nv_bfloat162*>(&sAhi[off])     = __halves2bfloat162(h0, h1); \
            *reinterpret_cast<__nv_bfloat162*>(&sAhi[off + 2]) = __halves2bfloat162(h2, h3); \
            *reinterpret_cast<__nv_bfloat162*>(&sAlo[off])     = __halves2bfloat162(l0, l1); \
            *reinterpret_cast<__nv_bfloat162*>(&sAlo[off + 2]) = __halves2bfloat162(l2, l3); \
        }                                                                              \
    } while (0)

    // ---- prologue: A stage 0 (chunk 0), B stages 0,1 (chunks 0,1), aR = chunk 1 ----
    LDA(0);
    CPB(0, 0); CP_COMMIT();        // group: chunk 0
    CONVSTORE(0);
    CPB(1, 1); CP_COMMIT();        // group: chunk 1
    LDA(1);
    CP_WAIT1();                    // chunk 0 B landed (chunk 1 may be in flight)
    __syncthreads();               // visibility of A stage 0 + B stage 0

    int bs = 0;                    // B stage of current chunk (= i % 3)
    for (int i = 0; i < NC; i++) {
        const int pa = i & 1;      // A stage of current chunk
        const int ab = pa * STG_ELEM;
        const int bb = bs * STG_ELEM;

        // ---- producers first (targets last read at iter i-1, protected by its barrier) ----
        if (i + 1 < NC) CONVSTORE(pa ^ 1);           // A chunk i+1 (from aR)
        int bnext = bs + 2; if (bnext >= 3) bnext -= 3;
        if (i + 2 < NC) { CPB(i + 2, bnext); }       // B chunk i+2
        CP_COMMIT();                                 // always commit (empty ok)
        if (i + 2 < NC) { LDA(i + 2); }

        // ---- MMA on A stage pa, B stage bs (overlaps chunk i+1's B in flight) ----
#pragma unroll
        for (int ks = 0; ks < KC; ks += 16) {
            uint32_t ah[2][4], al[2][4];
#pragma unroll
            for (int mi = 0; mi < 2; mi++) {
                int r = wm * 32 + mi * 16 + g;
                int c = ks + tg * 2;
                ah[mi][0] = *reinterpret_cast<const uint32_t*>(&sAhi[ab + r * ASTR + c]);
                ah[mi][1] = *reinterpret_cast<const uint32_t*>(&sAhi[ab + (r + 8) * ASTR + c]);
                ah[mi][2] = *reinterpret_cast<const uint32_t*>(&sAhi[ab + r * ASTR + c + 8]);
                ah[mi][3] = *reinterpret_cast<const uint32_t*>(&sAhi[ab + (r + 8) * ASTR + c + 8]);
                al[mi][0] = *reinterpret_cast<const uint32_t*>(&sAlo[ab + r * ASTR + c]);
                al[mi][1] = *reinterpret_cast<const uint32_t*>(&sAlo[ab + (r + 8) * ASTR + c]);
                al[mi][2] = *reinterpret_cast<const uint32_t*>(&sAlo[ab + r * ASTR + c + 8]);
                al[mi][3] = *reinterpret_cast<const uint32_t*>(&sAlo[ab + (r + 8) * ASTR + c + 8]);
            }
            uint32_t bhf[8][2], blf[8][2];
#pragma unroll
            for (int ni = 0; ni < 8; ni++) {
                int nn = wn * 64 + ni * 8 + g;
                bhf[ni][0] = *reinterpret_cast<const uint32_t*>(&sBhi[bb + nn * ASTR + ks + tg * 2]);
                bhf[ni][1] = *reinterpret_cast<const uint32_t*>(&sBhi[bb + nn * ASTR + ks + tg * 2 + 8]);
                blf[ni][0] = *reinterpret_cast<const uint32_t*>(&sBlo[bb + nn * ASTR + ks + tg * 2]);
                blf[ni][1] = *reinterpret_cast<const uint32_t*>(&sBlo[bb + nn * ASTR + ks + tg * 2 + 8]);
            }
#pragma unroll
            for (int ni = 0; ni < 8; ni++)
#pragma unroll
                for (int mi = 0; mi < 2; mi++)
                    MMA_BF16(acc[mi][ni], ah[mi], bhf[ni][0], bhf[ni][1]);   // hi*hi
#pragma unroll
            for (int ni = 0; ni < 8; ni++)
#pragma unroll
                for (int mi = 0; mi < 2; mi++)
                    MMA_BF16(acc[mi][ni], al[mi], bhf[ni][0], bhf[ni][1]);   // lo*hi
#pragma unroll
            for (int ni = 0; ni < 8; ni++)
#pragma unroll
                for (int mi = 0; mi < 2; mi++)
                    MMA_BF16(acc[mi][ni], ah[mi], blf[ni][0], blf[ni][1]);   // hi*lo
        }
        CP_WAIT1();                              // chunk i+1's B group retired (late wait)
        __syncthreads();                         // single barrier per chunk
        bs++; if (bs == 3) bs = 0;
    }

    // ---- epilogue phase 1: stage logits into smem tile [128][LSTR] ----
    float* sL = reinterpret_cast<float*>(sm);    // 128*130*4 = 66560 B <= 102400 B
#pragma unroll
    for (int mi = 0; mi < 2; mi++)
#pragma unroll
        for (int ni = 0; ni < 8; ni++) {
            int r = wm * 32 + mi * 16 + g;
            int c = wn * 64 + ni * 8 + tg * 2;
            sL[r * LSTR + c]           = acc[mi][ni][0];
            sL[r * LSTR + c + 1]       = acc[mi][ni][1];
            sL[(r + 8) * LSTR + c]     = acc[mi][ni][2];
            sL[(r + 8) * LSTR + c + 1] = acc[mi][ni][3];
        }
    __syncthreads();

    // ---- epilogue phase 2: fused gate (identical math to the old gate_kernel) ----
    {
        const int e0 = 2 * lane, e1 = 2 * lane + 1;
        float li0 = 0.f, li1 = 0.f, ll0 = 0.f, ll1 = 0.f;

        for (int it = 0; it < 16; it++) {
            const int lrow = wid * 16 + it;
            const int t    = row0 + lrow;
            const float* rowp = sL + lrow * LSTR;
            float cl0 = rowp[e0],      cl1 = rowp[e1];
            float rn0 = rowp[64 + e0], rn1 = rowp[64 + e1];
            float2 nz = *reinterpret_cast<const float2*>(noise + (size_t)t * N_EXP + e0);

            float sp0 = fmaxf(rn0, 0.f) + log1pf(expf(-fabsf(rn0))) + 0.01f;
            float sp1 = fmaxf(rn1, 0.f) + log1pf(expf(-fabsf(rn1))) + 0.01f;
            float ny0 = cl0 + nz.x * sp0;
            float ny1 = cl1 + nz.y * sp1;

            float bv; int bi;
            if (ny0 >= ny1) { bv = ny0; bi = e0; } else { bv = ny1; bi = e1; }
            warp_argmax(bv, bi);
            float m1 = bv; int j1 = bi;

            float w0 = (e0 == j1) ? -3.4e38f : ny0;
            float w1 = (e1 == j1) ? -3.4e38f : ny1;
            if (w0 >= w1) { bv = w0; bi = e0; } else { bv = w1; bi = e1; }
            warp_argmax(bv, bi);
            float m2 = bv; int j2 = bi;

            w0 = (e0 == j2) ? -3.4e38f : w0;
            w1 = (e1 == j2) ? -3.4e38f : w1;
            if (w0 >= w1) { bv = w0; bi = e0; } else { bv = w1; bi = e1; }
            warp_argmax(bv, bi);
            float m3 = bv;

            bool flagged = (m1 - m2 < TAU) || (m2 - m3 < TAU);
            if (flagged) {
                if (lane == 0) {
                    int s = atomicAdd(&g_nflag, 1);
                    g_flag[s] = t;
                }
                continue;
            }

            float ee  = expf(m2 - m1);
            float inv = 1.f / (1.f + ee);
            float gg0 = inv, gg1 = ee * inv;

            if (lane == 0) {
                out[2 * t]                    = (float)j1;
                out[2 * t + 1]                = (float)j2;
                out[2 * N_TOKENS + 2 * t]     = gg0;
                out[2 * N_TOKENS + 2 * t + 1] = gg1;
            }

            if (e0 == j1) li0 += gg0; else if (e0 == j2) li0 += gg1;
            if (e1 == j1) li1 += gg0; else if (e1 == j2) li1 += gg1;

            float thr0 = (ny0 > m3) ? m3 : m2;
            float thr1 = (ny1 > m3) ? m3 : m2;
            ll0 += normcdff((cl0 - thr0) / sp0);
            ll1 += normcdff((cl1 - thr1) / sp1);
        }

        atomicAdd(&s_imp[e0], li0);  atomicAdd(&s_imp[e1], li1);
        atomicAdd(&s_load[e0], ll0); atomicAdd(&s_load[e1], ll1);
        __syncthreads();
        if (tid < N_EXP) {
            atomicAdd(&g_imp[tid],  s_imp[tid]);
            atomicAdd(&g_load[tid], s_load[tid]);
        }
    }
#undef CPB
#undef LDA
#undef CONVSTORE
}

// ---------------- refine: fp64-exact logits, 128 token-slots x 128 cols ----------------
__global__ void __launch_bounds__(256) refine_kernel(const float* __restrict__ inp) {
    const int tid  = threadIdx.x;
    const int lane = tid & 31;
    const int W    = blockIdx.x * 8 + (tid >> 5);   // 0..16383
    const int slot = W >> 7;                        // 128 token slots
    const int n    = W & 127;                       // output column
    const int nf   = g_nflag;

    for (int ii = slot; ii < nf; ii += 128) {
        const int t = g_flag[ii];
        const float4* ap = reinterpret_cast<const float4*>(inp + (size_t)t * D_MODEL);
        const float4* wp = reinterpret_cast<const float4*>(g_wt + (size_t)n * D_MODEL);
        double c0 = 0, c1 = 0, c2 = 0, c3 = 0;
#pragma unroll 8
        for (int j = 0; j < D_MODEL / 128; j++) {   // 32 iters, lane-strided float4
            float4 a = ap[j * 32 + lane];
            float4 b = wp[j * 32 + lane];
            c0 = fma((double)a.x, (double)b.x, c0);
            c1 = fma((double)a.y, (double)b.y, c1);
            c2 = fma((double)a.z, (double)b.z, c2);
            c3 = fma((double)a.w, (double)b.w, c3);
        }
        double s = (c0 + c1) + (c2 + c3);
#pragma unroll
        for (int o = 16; o; o >>= 1) s += __shfl_down_sync(0xffffffffu, s, o);
        if (lane == 0) g_logits[(size_t)t * N_OUT + n] = (float)s;
    }
}

// ---------------- refine2: gate math on exact logits (warp per flagged token) ----------------
__global__ void __launch_bounds__(256) refine2_kernel(const float* __restrict__ noise,
                                                      float* __restrict__ out) {
    const int tid  = threadIdx.x;
    const int lane = tid & 31;
    const int W    = blockIdx.x * 8 + (tid >> 5);
    const int nW   = gridDim.x * 8;
    const int nf   = g_nflag;
    const int e0 = 2 * lane, e1 = 2 * lane + 1;

    for (int ii = W; ii < nf; ii += nW) {
        const int t = g_flag[ii];
        const float* rowp = g_logits + (size_t)t * N_OUT;
        float cl0 = rowp[e0], cl1 = rowp[e1];
        float rn0 = rowp[64 + e0], rn1 = rowp[64 + e1];
        float nz0 = noise[(size_t)t * N_EXP + e0];
        float nz1 = noise[(size_t)t * N_EXP + e1];

        float sp0 = fmaxf(rn0, 0.f) + log1pf(expf(-fabsf(rn0))) + 0.01f;
        float sp1 = fmaxf(rn1, 0.f) + log1pf(expf(-fabsf(rn1))) + 0.01f;
        float ny0 = cl0 + nz0 * sp0;
        float ny1 = cl1 + nz1 * sp1;

        float bv; int bi;
        if (ny0 >= ny1) { bv = ny0; bi = e0; } else { bv = ny1; bi = e1; }
        warp_argmax(bv, bi);
        float m1 = bv; int j1 = bi;

        float w0 = (e0 == j1) ? -3.4e38f : ny0;
        float w1 = (e1 == j1) ? -3.4e38f : ny1;
        if (w0 >= w1) { bv = w0; bi = e0; } else { bv = w1; bi = e1; }
        warp_argmax(bv, bi);
        float m2 = bv; int j2 = bi;

        w0 = (e0 == j2) ? -3.4e38f : w0;
        w1 = (e1 == j2) ? -3.4e38f : w1;
        if (w0 >= w1) { bv = w0; bi = e0; } else { bv = w1; bi = e1; }
        warp_argmax(bv, bi);
        float m3 = bv;

        float ee  = expf(m2 - m1);
        float inv = 1.f / (1.f + ee);
        float gg0 = inv, gg1 = ee * inv;

        if (lane == 0) {
            out[2 * t]                    = (float)j1;
            out[2 * t + 1]                = (float)j2;
            out[2 * N_TOKENS + 2 * t]     = gg0;
            out[2 * N_TOKENS + 2 * t + 1] = gg1;
        }

        float li0 = 0.f, li1 = 0.f;
        if (e0 == j1) li0 = gg0; else if (e0 == j2) li0 = gg1;
        if (e1 == j1) li1 = gg0; else if (e1 == j2) li1 = gg1;

        float thr0 = (ny0 > m3) ? m3 : m2;
        float thr1 = (ny1 > m3) ? m3 : m2;
        float ll0 = normcdff((cl0 - thr0) / sp0);
        float ll1 = normcdff((cl1 - thr1) / sp1);

        if (li0 != 0.f) atomicAdd(&g_imp[e0], li0);
        if (li1 != 0.f) atomicAdd(&g_imp[e1], li1);
        atomicAdd(&g_load[e0], ll0);
        atomicAdd(&g_load[e1], ll1);
    }
}

// ---------------- loss: cv^2(importance) + cv^2(load), warp-parallel ----------------
__global__ void loss_kernel(float* __restrict__ out) {
    const int lane = threadIdx.x;   // 32 threads
    float loss = 0.f;
#pragma unroll
    for (int pass = 0; pass < 2; pass++) {
        const float* a = pass ? g_load : g_imp;
        float x0 = a[lane], x1 = a[lane + 32];
        float s = x0 + x1;
#pragma unroll
        for (int o = 16; o; o >>= 1) s += __shfl_xor_sync(0xffffffffu, s, o);
        float mean = s * (1.f / 64.f);
        float d0 = x0 - mean, d1 = x1 - mean;
        float v = d0 * d0 + d1 * d1;
#pragma unroll
        for (int o = 16; o; o >>= 1) v += __shfl_xor_sync(0xffffffffu, v, o);
        v *= (1.f / 63.f);
        loss += v / (mean * mean + 1e-10f);
    }
    if (lane == 0) out[2 * N_TOKENS * 2] = loss;   // index 65536
}

// ---------------- launch ----------------
extern "C" void kernel_launch(void* const* d_in, const int* in_sizes, int n_in,
                              void* d_out, int out_size) {
    const float* inp   = (const float*)d_in[0];
    const float* wg    = (const float*)d_in[1];
    const float* wn    = (const float*)d_in[2];
    const float* noise = (const float*)d_in[3];
    float* out = (float*)d_out;

    static bool attr_done = false;
    if (!attr_done) {
        cudaFuncSetAttribute(gemm_kernel, cudaFuncAttributeMaxDynamicSharedMemorySize,
                             GSMEM);
        attr_done = true;
    }

    prep_kernel<<<128, 256>>>(wg, wn);
    gemm_kernel<<<N_TOKENS / 128, 256, GSMEM>>>(inp, noise, out);
    refine_kernel<<<2048, 256>>>(inp);
    refine2_kernel<<<64, 256>>>(noise, out);
    loss_kernel<<<1, 32>>>(out);
}